// round 17
// baseline (speedup 1.0000x reference)
#include <cuda_runtime.h>
#include <cuda_fp16.h>
#include <stdint.h>

// ---------------- problem constants ----------------
#define N_TOK 4096
#define DIM   512
#define ODIM  512
#define NEXP  8
#define TOPK  2

// ---------------- GEMM tiling ----------------
#define BM 128
#define BN 128
#define BK 32
#define NCH (DIM / BK)                      // 16 k-chunks
#define MAXROWS (N_TOK * TOPK + NEXP * BM)  // 9216
#define MTILES  (MAXROWS / BM)              // 72
#define NTILES  (ODIM / BN)                 // 4

typedef unsigned int u32;
typedef unsigned long long u64;

// ---------------- device scratch ----------------
__device__ int   g_counts[NEXP];            // zero at load; route resets for next replay
__device__ int   g_offsets[NEXP + 1];
__device__ int   g_row_token[MAXROWS];
__device__ int   g_top_e[N_TOK * TOPK];
__device__ int   g_tok_rows[N_TOK * TOPK];
__device__ float g_tok_w[N_TOK * TOPK];
__device__ float g_y[(size_t)MAXROWS * ODIM];
// weights, fp16, ORIGINAL [layer][e][k][n] layout (no transpose)
__device__ __half g_w[(size_t)3 * NEXP * DIM * ODIM];
// activations: token-order fp16 (layer-0 input), row-order ping-pong
__device__ __half g_ax[(size_t)N_TOK * DIM];
__device__ __half g_a[2][(size_t)MAXROWS * DIM];

// ---------------- PTX helpers ----------------
__device__ __forceinline__ u32 smem_u32(const void* p) {
    u32 a;
    asm("{ .reg .u64 t; cvta.to.shared.u64 t, %1; cvt.u32.u64 %0, t; }" : "=r"(a) : "l"(p));
    return a;
}
__device__ __forceinline__ void cp16(u32 dst, const void* src) {
    asm volatile("cp.async.cg.shared.global [%0], [%1], 16;" :: "r"(dst), "l"(src) : "memory");
}
__device__ __forceinline__ void cp_commit() {
    asm volatile("cp.async.commit_group;" ::: "memory");
}
template <int N>
__device__ __forceinline__ void cp_wait() {
    asm volatile("cp.async.wait_group %0;" :: "n"(N) : "memory");
}
#define LDM_X4(d, addr)                                                        \
    asm volatile("ldmatrix.sync.aligned.m8n8.x4.shared.b16 {%0,%1,%2,%3}, [%4];" \
        : "=r"((d)[0]), "=r"((d)[1]), "=r"((d)[2]), "=r"((d)[3]) : "r"(addr))
#define LDM_X4T(d, addr)                                                       \
    asm volatile("ldmatrix.sync.aligned.m8n8.x4.trans.shared.b16 {%0,%1,%2,%3}, [%4];" \
        : "=r"((d)[0]), "=r"((d)[1]), "=r"((d)[2]), "=r"((d)[3]) : "r"(addr))
#define MMA16816(c, a, bv0, bv1)                                               \
    asm volatile("mma.sync.aligned.m16n8k16.row.col.f32.f16.f16.f32 "          \
        "{%0,%1,%2,%3}, {%4,%5,%6,%7}, {%8,%9}, {%0,%1,%2,%3};"                \
        : "+f"((c)[0]), "+f"((c)[1]), "+f"((c)[2]), "+f"((c)[3])               \
        : "r"((a)[0]), "r"((a)[1]), "r"((a)[2]), "r"((a)[3]), "r"(bv0), "r"(bv1))

__device__ __forceinline__ u32 pack_h2(__half a, __half b) {
    return (u32)__half_as_ushort(a) | ((u32)__half_as_ushort(b) << 16);
}
// A tile swizzle: [128 rows][32 k] fp16, row=64B, 4 chunks of 16B
__device__ __forceinline__ u32 swz_off(int r, int c) {
    return (u32)(r * 64 + ((c ^ ((r >> 1) & 3)) << 4));
}
// B tile swizzle: [32 k rows][128 n] fp16, row=256B, 16 chunks of 16B
__device__ __forceinline__ u32 bswz(int r, int c) {
    return (u32)(r * 256 + (((c) ^ (r & 7)) << 4));
}

// ---------------- fused gating + activation fp16 convert ----------------
// one warp per token: gate dot-products AND x -> g_ax fp16 conversion
__global__ void gate_convert_kernel(const float* __restrict__ x,
                                    const float* __restrict__ gw,
                                    const float* __restrict__ gb) {
    int warp = (blockIdx.x * blockDim.x + threadIdx.x) >> 5;
    int lane = threadIdx.x & 31;
    if (warp >= N_TOK) return;
    const float* xr = x + (size_t)warp * DIM;
    __half* axr = g_ax + (size_t)warp * DIM;

    float acc[NEXP];
#pragma unroll
    for (int e = 0; e < NEXP; ++e) acc[e] = 0.f;
    for (int i = lane; i < DIM; i += 32) {
        float xv = xr[i];
        axr[i] = __float2half_rn(xv);
        const float4* g4 = (const float4*)(gw + (size_t)i * NEXP);
        float4 a = g4[0], b = g4[1];
        acc[0] += xv * a.x; acc[1] += xv * a.y; acc[2] += xv * a.z; acc[3] += xv * a.w;
        acc[4] += xv * b.x; acc[5] += xv * b.y; acc[6] += xv * b.z; acc[7] += xv * b.w;
    }
#pragma unroll
    for (int e = 0; e < NEXP; ++e)
#pragma unroll
        for (int off = 16; off; off >>= 1)
            acc[e] += __shfl_xor_sync(0xffffffffu, acc[e], off);

    if (lane == 0) {
        float lg[NEXP], mx = -1e30f;
#pragma unroll
        for (int e = 0; e < NEXP; ++e) { lg[e] = acc[e] + gb[e]; mx = fmaxf(mx, lg[e]); }
        float p[NEXP], s = 0.f;
#pragma unroll
        for (int e = 0; e < NEXP; ++e) { p[e] = expf(lg[e] - mx); s += p[e]; }
        float inv = 1.0f / s;
        int i0 = 0;
#pragma unroll
        for (int e = 1; e < NEXP; ++e) if (lg[e] > lg[i0]) i0 = e;
        int i1 = -1;
#pragma unroll
        for (int e = 0; e < NEXP; ++e)
            if (e != i0 && (i1 < 0 || lg[e] > lg[i1])) i1 = e;
        // Faithful quirk: slot j combine weight is probs[n, j]
        g_top_e[warp * 2 + 0] = i0;
        g_top_e[warp * 2 + 1] = i1;
        g_tok_w[warp * 2 + 0] = p[0] * inv;
        g_tok_w[warp * 2 + 1] = p[1] * inv;
        atomicAdd(&g_counts[i0], 1);
        atomicAdd(&g_counts[i1], 1);
    }
}

// ---------------- weight convert: pure streaming fp32 -> fp16 ----------------
__global__ void convert_w_kernel(const float* __restrict__ w1,
                                 const float* __restrict__ w2,
                                 const float* __restrict__ w3) {
    const size_t PER_L = (size_t)NEXP * DIM * ODIM / 4;   // float4s per layer
    const size_t TOTAL = 3 * PER_L;
    size_t stride = (size_t)gridDim.x * blockDim.x;
#pragma unroll 1
    for (size_t i = (size_t)blockIdx.x * blockDim.x + threadIdx.x; i < TOTAL; i += stride) {
        int l = (int)(i / PER_L);
        size_t j = i - (size_t)l * PER_L;
        const float* W = (l == 0) ? w1 : (l == 1) ? w2 : w3;
        float4 v = ((const float4*)W)[j];
        ((uint2*)g_w)[i] =
            make_uint2(pack_h2(__float2half_rn(v.x), __float2half_rn(v.y)),
                       pack_h2(__float2half_rn(v.z), __float2half_rn(v.w)));
    }
}

// ---------------- route: offsets + ballot-aggregated scatter + pad fill ----------------
__global__ void route_kernel() {
    __shared__ int soff[NEXP + 1];
    __shared__ int scnt[NEXP];
    __shared__ int scur[NEXP];
    int tid = threadIdx.x;
    int lane = tid & 31;
    if (tid < NEXP) {
        scnt[tid] = g_counts[tid];
        scur[tid] = 0;
    }
    __syncthreads();
    if (tid == 0) {
        int off = 0;
#pragma unroll
        for (int e = 0; e < NEXP; ++e) {
            soff[e] = off;
            g_offsets[e] = off;
            off += ((scnt[e] + BM - 1) / BM) * BM;
        }
        soff[NEXP] = off;
        g_offsets[NEXP] = off;
    }
    __syncthreads();

    // scatter: warp-aggregated smem atomics
    for (int i = tid; i < N_TOK * TOPK; i += blockDim.x) {
        int e = g_top_e[i];
        int r = 0;
#pragma unroll
        for (int e0 = 0; e0 < NEXP; ++e0) {
            u32 mask = __ballot_sync(0xffffffffu, e == e0);
            if (e == e0) {
                int leader = __ffs(mask) - 1;
                int base = 0;
                if (lane == leader) base = atomicAdd(&scur[e0], __popc(mask));
                base = __shfl_sync(mask, base, leader);
                r = soff[e0] + base + __popc(mask & ((1u << lane) - 1u));
            }
        }
        g_row_token[r] = i >> 1;
        g_tok_rows[i] = r;
    }
    __syncthreads();

    // mark padding rows (-1) and reset counts for next graph replay
    for (int j = tid; j < NEXP * BM; j += blockDim.x) {
        int e = j >> 7, k = j & (BM - 1);
        int start = soff[e] + scnt[e];
        if (start + k < soff[e + 1]) g_row_token[start + k] = -1;
    }
    if (tid < NEXP) g_counts[tid] = 0;
}

// ---------------- HMMA grouped GEMM (single-pass fp16, fp32 accum) ----------------
// LAYER 0: A = g_ax (gathered via g_row_token) -> g_a[1]
// LAYER 1: A = g_a[1] -> g_a[0]
// LAYER 2: A = g_a[0] -> g_y (fp32)
#define OFF_A  0
#define OFF_B  8192
#define STAGE_BYTES 16384
#define NSTAGE 4
#define SMEM_NEED (NSTAGE * STAGE_BYTES + 128)

template <int LAYER>
__global__ void __launch_bounds__(256, 2)
moe_gemm_mma(const float* __restrict__ Bias) {
    constexpr bool GATHER = (LAYER == 0);
    const __half* Ain = (LAYER == 1) ? g_a[1] : g_a[0];  // unused for LAYER 0
    __half* Oa = (LAYER == 0) ? g_a[1] : g_a[0];

    int total = g_offsets[NEXP];
    int mbase = blockIdx.y * BM;
    if (mbase >= total) return;
    int e = 0;
    while (e < NEXP - 1 && mbase >= g_offsets[e + 1]) e++;
    int nbase = blockIdx.x * BN;

    extern __shared__ char smraw[];
    u32 sraw = smem_u32(smraw);
    u32 sbase = (sraw + 127u) & ~127u;
    __shared__ int rtok[BM];

    int tid = threadIdx.x;
    int wid = tid >> 5, lid = tid & 31;
    int wm = wid & 3, wn = wid >> 2;

    if (GATHER) {
        if (tid < BM) {
            int t = g_row_token[mbase + tid];
            rtok[tid] = (t < 0) ? 0 : t;
        }
        __syncthreads();
    }

    // weights in [k][n]: row k has ODIM halves
    const __half* Wp = g_w + (size_t)(LAYER * NEXP + e) * DIM * ODIM;

    // A cp.async: 512 chunks = 128 rows x 4 chunks; 2 per thread
    int ar0 = tid >> 2, ac0 = tid & 3;
    int ar1 = ar0 + 64;
    u32 da0 = swz_off(ar0, ac0), da1 = swz_off(ar1, ac0);
    const __half* asrc0;
    const __half* asrc1;
    if (GATHER) {
        asrc0 = g_ax + (size_t)rtok[ar0] * DIM + ac0 * 8;
        asrc1 = g_ax + (size_t)rtok[ar1] * DIM + ac0 * 8;
    } else {
        asrc0 = Ain + (size_t)(mbase + ar0) * DIM + ac0 * 8;
        asrc1 = Ain + (size_t)(mbase + ar1) * DIM + ac0 * 8;
    }

    // B cp.async: 512 chunks = 32 k-rows x 16 chunks; 2 per thread
    int br0 = tid >> 4, bc = tid & 15;
    int br1 = br0 + 16;
    u32 db0 = bswz(br0, bc), db1 = bswz(br1, bc);
    const __half* bsrc0 = Wp + (size_t)br0 * ODIM + nbase + bc * 8;
    const __half* bsrc1 = Wp + (size_t)br1 * ODIM + nbase + bc * 8;

    float acc[2][8][4];
#pragma unroll
    for (int i = 0; i < 2; ++i)
#pragma unroll
        for (int j = 0; j < 8; ++j)
#pragma unroll
            for (int q = 0; q < 4; ++q) acc[i][j][q] = 0.f;

#define PREFETCH(ch) do {                                                      \
    u32 sb = sbase + ((ch) % NSTAGE) * STAGE_BYTES;                            \
    int kk = (ch) * BK;                                                        \
    cp16(sb + OFF_A + da0, asrc0 + kk);                                        \
    cp16(sb + OFF_A + da1, asrc1 + kk);                                        \
    cp16(sb + OFF_B + db0, bsrc0 + (size_t)kk * ODIM);                         \
    cp16(sb + OFF_B + db1, bsrc1 + (size_t)kk * ODIM);                         \
    cp_commit();                                                               \
} while (0)

    PREFETCH(0);
    PREFETCH(1);
    PREFETCH(2);

    for (int ch = 0; ch < NCH; ++ch) {
        if (ch < NCH - 2)       cp_wait<2>();
        else if (ch == NCH - 2) cp_wait<1>();
        else                    cp_wait<0>();
        __syncthreads();
        if (ch + 3 < NCH) PREFETCH(ch + 3);

        u32 sb = sbase + (ch % NSTAGE) * STAGE_BYTES;
#pragma unroll
        for (int s = 0; s < 2; ++s) {
            u32 af[2][4];
#pragma unroll
            for (int mt = 0; mt < 2; ++mt) {
                int r = wm * 32 + mt * 16 + (lid & 15);
                int chunk = s * 2 + (lid >> 4);
                LDM_X4(af[mt], sb + OFF_A + swz_off(r, chunk));
            }
            int grp = lid >> 3, rr = lid & 7;
            int krow = s * 16 + ((grp & 1) << 3) + rr;
#pragma unroll
            for (int p = 0; p < 4; ++p) {
                int nch = ((wn * 64 + p * 16) >> 3) + (grp >> 1);
                u32 bh[4];
                LDM_X4T(bh, sb + OFF_B + bswz(krow, nch));
#pragma unroll
                for (int mt = 0; mt < 2; ++mt) {
                    MMA16816(acc[mt][2 * p + 0], af[mt], bh[0], bh[1]);
                    MMA16816(acc[mt][2 * p + 1], af[mt], bh[2], bh[3]);
                }
            }
        }
    }
#undef PREFETCH

    // epilogue: bias + relu, write next layer fp16 (or fp32 y)
#pragma unroll
    for (int mt = 0; mt < 2; ++mt) {
#pragma unroll
        for (int nt = 0; nt < 8; ++nt) {
            int row = mbase + wm * 32 + mt * 16 + (lid >> 2);
            int n0 = nbase + wn * 64 + nt * 8 + (lid & 3) * 2;
            float bb0 = __ldg(Bias + e * ODIM + n0);
            float bb1 = __ldg(Bias + e * ODIM + n0 + 1);
            float v00 = fmaxf(acc[mt][nt][0] + bb0, 0.f);
            float v01 = fmaxf(acc[mt][nt][1] + bb1, 0.f);
            float v10 = fmaxf(acc[mt][nt][2] + bb0, 0.f);
            float v11 = fmaxf(acc[mt][nt][3] + bb1, 0.f);
            if (LAYER < 2) {
                *(u32*)(Oa + (size_t)row * DIM + n0) =
                    pack_h2(__float2half_rn(v00), __float2half_rn(v01));
                *(u32*)(Oa + (size_t)(row + 8) * DIM + n0) =
                    pack_h2(__float2half_rn(v10), __float2half_rn(v11));
            } else {
                *(float2*)(g_y + (size_t)row * ODIM + n0)       = make_float2(v00, v01);
                *(float2*)(g_y + (size_t)(row + 8) * ODIM + n0) = make_float2(v10, v11);
            }
        }
    }
}

// ---------------- combine ----------------
__global__ void combine_kernel(float* __restrict__ out) {
    int tok = blockIdx.x;
    int r0 = g_tok_rows[tok * 2 + 0];
    int r1 = g_tok_rows[tok * 2 + 1];
    float w0 = g_tok_w[tok * 2 + 0];
    float w1 = g_tok_w[tok * 2 + 1];
    const float4* y0 = (const float4*)(g_y + (size_t)r0 * ODIM);
    const float4* y1 = (const float4*)(g_y + (size_t)r1 * ODIM);
    float4* o = (float4*)(out + (size_t)tok * ODIM);
    for (int c = threadIdx.x; c < ODIM / 4; c += blockDim.x) {
        float4 a = y0[c], b = y1[c];
        o[c] = make_float4(w0 * a.x + w1 * b.x, w0 * a.y + w1 * b.y,
                           w0 * a.z + w1 * b.z, w0 * a.w + w1 * b.w);
    }
}

// ---------------- launch ----------------
extern "C" void kernel_launch(void* const* d_in, const int* in_sizes, int n_in,
                              void* d_out, int out_size) {
    const float* x  = (const float*)d_in[0];
    const float* gw = (const float*)d_in[1];
    const float* gb = (const float*)d_in[2];
    const float* w1 = (const float*)d_in[3];
    const float* b1 = (const float*)d_in[4];
    const float* w2 = (const float*)d_in[5];
    const float* b2 = (const float*)d_in[6];
    const float* w3 = (const float*)d_in[7];
    const float* b3 = (const float*)d_in[8];
    float* out = (float*)d_out;

    cudaFuncSetAttribute(moe_gemm_mma<0>, cudaFuncAttributeMaxDynamicSharedMemorySize, SMEM_NEED);
    cudaFuncSetAttribute(moe_gemm_mma<1>, cudaFuncAttributeMaxDynamicSharedMemorySize, SMEM_NEED);
    cudaFuncSetAttribute(moe_gemm_mma<2>, cudaFuncAttributeMaxDynamicSharedMemorySize, SMEM_NEED);

    gate_convert_kernel<<<N_TOK / 8, 256>>>(x, gw, gb);   // gate + x->fp16
    convert_w_kernel<<<1536, 256>>>(w1, w2, w3);
    route_kernel<<<1, 1024>>>();

    dim3 grid(NTILES, MTILES);
    moe_gemm_mma<0><<<grid, 256, SMEM_NEED>>>(b1);
    moe_gemm_mma<1><<<grid, 256, SMEM_NEED>>>(b2);
    moe_gemm_mma<2><<<grid, 256, SMEM_NEED>>>(b3);

    combine_kernel<<<N_TOK, 128>>>(out);
}